// round 1
// baseline (speedup 1.0000x reference)
#include <cuda_runtime.h>
#include <cstdint>
#include <cstddef>

// Problem constants (fixed by the reference)
#define Vv 10000
#define Bb 16
#define Tt 128
#define Dd 256
#define CLUSTER 8
#define NCOL 32              // Dd / CLUSTER  columns per CTA
#define NTHREADS 512
#define GRPS 16              // threads per column
#define NDPT 16              // d-elements per thread (Dd / GRPS)

__device__ __forceinline__ uint32_t my_cluster_rank() {
    uint32_t r;
    asm("mov.u32 %0, %%cluster_ctarank;" : "=r"(r));
    return r;
}

__device__ __forceinline__ void cluster_sync_() {
    asm volatile("barrier.cluster.arrive.aligned;" ::: "memory");
    asm volatile("barrier.cluster.wait.aligned;" ::: "memory");
}

__device__ __forceinline__ void remote_store_f32(uint32_t laddr, uint32_t rank, float v) {
    uint32_t r;
    asm volatile("mapa.shared::cluster.u32 %0, %1, %2;" : "=r"(r) : "r"(laddr), "r"(rank));
    asm volatile("st.shared::cluster.f32 [%0], %1;" :: "r"(r), "f"(v) : "memory");
}

// sum across the 16 threads of one column (lanes grouped by dgrp bits 0..3)
__device__ __forceinline__ float grp16_sum(float v) {
    v += __shfl_xor_sync(0xffffffffu, v, 1);
    v += __shfl_xor_sync(0xffffffffu, v, 2);
    v += __shfl_xor_sync(0xffffffffu, v, 4);
    v += __shfl_xor_sync(0xffffffffu, v, 8);
    return v;
}

// One plastic layer forward + hebb update for this thread's (16 d, 1 e) tile.
// yin_s: smem pointer to the full 256-float input-state vector of this layer.
__device__ __forceinline__ float layer_step(
    const float* __restrict__ yin_s,
    float (&h)[NDPT], const float (&w)[NDPT], const float (&a)[NDPT],
    float inp_e, float eta, float one_minus_eta, int dbase)
{
    float yin[NDPT];
#pragma unroll
    for (int i = 0; i < NDPT; i += 4) {
        float4 v = *reinterpret_cast<const float4*>(yin_s + dbase + i);
        yin[i] = v.x; yin[i + 1] = v.y; yin[i + 2] = v.z; yin[i + 3] = v.w;
    }
    float acc = 0.f;
#pragma unroll
    for (int i = 0; i < NDPT; i++)
        acc = fmaf(yin[i], fmaf(a[i], h[i], w[i]), acc);
    acc = grp16_sum(acc);
    float yout = tanhf(acc + inp_e);
    float ey = eta * yout;
#pragma unroll
    for (int i = 0; i < NDPT; i++)
        h[i] = fmaf(h[i], one_minus_eta, yin[i] * ey);
    return yout;
}

__global__ void __launch_bounds__(NTHREADS, 1) __cluster_dims__(CLUSTER, 1, 1)
plastic_kernel(const int* __restrict__ x, const float* __restrict__ emb,
               const float* __restrict__ ws, const float* __restrict__ alphas,
               const float* __restrict__ etas, float* __restrict__ out)
{
    __shared__ __align__(16) float y0s[2][Dd];   // layer-0 state, double buffered by step parity
    __shared__ __align__(16) float y1s[2][Dd];   // layer-1 state
    __shared__ float stage[Dd * NCOL];           // 32 KB startup staging for W/alpha
    __shared__ int   xtok[Tt];
    __shared__ float redbuf[16];

    const int tid     = threadIdx.x;
    const int batch   = blockIdx.x >> 3;
    const int rank    = (int)my_cluster_rank();
    const int e_local = tid >> 4;            // 0..31
    const int dgrp    = tid & 15;            // 0..15
    const int e0      = rank * NCOL;
    const int eg      = e0 + e_local;
    const int dbase   = dgrp * NDPT;

    // init shared state
    if (tid < Dd) {
        y0s[0][tid] = 0.f; y0s[1][tid] = 0.f;
        y1s[0][tid] = 0.f; y1s[1][tid] = 0.f;
    }
    if (tid < Tt) xtok[tid] = x[batch * Tt + tid];

    const float eta0 = etas[0], eta1 = etas[1];
    const float om0 = 1.0f - eta0, om1 = 1.0f - eta1;

    // register-resident per-thread state
    float h0[NDPT], h1[NDPT], w0[NDPT], w1[NDPT], a0[NDPT], a1[NDPT];
#pragma unroll
    for (int i = 0; i < NDPT; i++) { h0[i] = 0.f; h1[i] = 0.f; }

    // Stage W/alpha slices (coalesced gmem -> smem -> regs)
#define STAGE_LOAD(reg, gptr)                                             \
    __syncthreads();                                                      \
    for (int idx = tid; idx < Dd * NCOL; idx += NTHREADS) {               \
        int d = idx >> 5, j = idx & 31;                                   \
        stage[idx] = (gptr)[d * Dd + e0 + j];                             \
    }                                                                     \
    __syncthreads();                                                      \
    _Pragma("unroll")                                                     \
    for (int i = 0; i < NDPT; i++) reg[i] = stage[(dbase + i) * NCOL + e_local];

    STAGE_LOAD(w0, ws)
    STAGE_LOAD(w1, ws + Dd * Dd)
    STAGE_LOAD(a0, alphas)
    STAGE_LOAD(a1, alphas + Dd * Dd)
    __syncthreads();

    const uint32_t y0a[2] = {
        (uint32_t)__cvta_generic_to_shared(&y0s[0][eg]),
        (uint32_t)__cvta_generic_to_shared(&y0s[1][eg]) };
    const uint32_t y1a[2] = {
        (uint32_t)__cvta_generic_to_shared(&y1s[0][eg]),
        (uint32_t)__cvta_generic_to_shared(&y1s[1][eg]) };

    cluster_sync_();   // all CTAs initialized before anyone broadcasts

    // ---- prologue: layer0 at t=0 (yin = 0 vector, inp = emb[x[0]]) ----
    {
        float inp = emb[(size_t)xtok[0] * Dd + eg];
        float y = layer_step(y0s[0], h0, w0, a0, inp, eta0, om0, dbase);
        if (dgrp < CLUSTER) remote_store_f32(y0a[1], (uint32_t)dgrp, y);
    }
    cluster_sync_();

    float* const outB = out + (size_t)batch * Tt * Dd;

    for (int t = 0; t < Tt; ++t) {
        const int cur = (t + 1) & 1;   // buffer holding y(t)
        const int prv = t & 1;         // buffer holding y(t-1)

        // prefetch embedding input for layer0(t+1)
        float inp0 = 0.f;
        if (t + 1 < Tt) inp0 = emb[(size_t)xtok[t + 1] * Dd + eg];

        // layer1(t): yin = y1(t-1), input = y0(t)
        float inp1 = y0s[cur][eg];
        float y1v = layer_step(y1s[prv], h1, w1, a1, inp1, eta1, om1, dbase);
        if (dgrp < CLUSTER) remote_store_f32(y1a[cur], (uint32_t)dgrp, y1v);

        // layer0(t+1): yin = y0(t), input = emb[x[t+1]]
        if (t + 1 < Tt) {
            float y0v = layer_step(y0s[cur], h0, w0, a0, inp0, eta0, om0, dbase);
            if (dgrp < CLUSTER) remote_store_f32(y0a[prv], (uint32_t)dgrp, y0v);
        }

        cluster_sync_();

        // ---- output for step t: softmax(sigmoid(y1(t))) over D, full copy local ----
        float ex = 0.f;
        if (tid < Dd) {
            float yv = y1s[cur][tid];
            float s = 1.0f / (1.0f + __expf(-yv));
            ex = __expf(s);
        }
        float wsum = ex;
#pragma unroll
        for (int o = 16; o >= 1; o >>= 1) wsum += __shfl_xor_sync(0xffffffffu, wsum, o);
        const int wid = tid >> 5, lane = tid & 31;
        if (lane == 0) redbuf[wid] = wsum;
        __syncthreads();
        float tot = 0.f;
#pragma unroll
        for (int k = 0; k < 8; k++) tot += redbuf[k];
        float inv = 1.0f / tot;
        if (tid >= e0 && tid < e0 + NCOL) {
            outB[(size_t)t * Dd + tid] = ex * inv;
        }
        // redbuf reuse next iter is protected by the next cluster_sync_ (full CTA barrier)
    }
}

extern "C" void kernel_launch(void* const* d_in, const int* in_sizes, int n_in,
                              void* d_out, int out_size) {
    const int*   x      = (const int*)d_in[0];
    const float* emb    = (const float*)d_in[1];
    const float* ws     = (const float*)d_in[2];
    const float* alphas = (const float*)d_in[3];
    const float* etas   = (const float*)d_in[4];
    plastic_kernel<<<Bb * CLUSTER, NTHREADS>>>(x, emb, ws, alphas, etas, (float*)d_out);
}